// round 9
// baseline (speedup 1.0000x reference)
#include <cuda_runtime.h>
#include <cuda_bf16.h>

// Problem shape (fixed for GAT_40870908789103)
#define Nn   50000
#define Ee   800000
#define Fin  128
#define Hh   8
#define Oo   8
#define HO   64          // H*O
#define NEG_SLOPE 0.2f
#define BCAP 96          // per-node bucket capacity; P(deg>96)~1e-40 for Poisson(16)

#define PROJ_BLOCKS ((Nn + 127) / 128)      // 391
#define BUCKET_BLOCKS 1024

// Scratch (no allocation allowed -> __device__ globals)
// NOTE: g_cursor relies on static zero-init + k_agg self-cleaning reset.
__device__ float g_Wh[(size_t)Nn * HO];       // projected features [N][64]
__device__ float g_ssrc[(size_t)Nn * Hh];     // a1 . Wh[n,h,:]
__device__ float g_sdst[(size_t)Nn * Hh];     // a2 . Wh[n,h,:]
__device__ int   g_cursor[Nn];                // per-node edge counts (zero-init)
__device__ int   g_bucket[(size_t)Nn * BCAP]; // SRC ids grouped by dst

// ---------------------------------------------------------------------------
// K1 (fused front): blocks [0, PROJ_BLOCKS) run the projection GEMM
// (R3 inner loop — verbatim; best measured config). Remaining blocks
// grid-stride over edges bucketing src ids by dst. Proj is FMA/LDS-bound,
// bucket is memory/atomic-bound -> they overlap on different pipes.
// ---------------------------------------------------------------------------
#define FCH 32                      // f-chunk
#define HS_STRIDE 33                // 32 + 1 pad: bank = (row+f) % 32

__global__ __launch_bounds__(128) void k_front(const float* __restrict__ h,
                                               const float* __restrict__ W,
                                               const float* __restrict__ a1,
                                               const float* __restrict__ a2,
                                               const int* __restrict__ src,
                                               const int* __restrict__ dst) {
    if (blockIdx.x >= PROJ_BLOCKS) {
        // ---- bucket branch: grid-stride over edges ----
        const int stride = BUCKET_BLOCKS * 128;
        int e = (blockIdx.x - PROJ_BLOCKS) * 128 + threadIdx.x;
        for (; e < Ee; e += stride) {
            int d = __ldg(&dst[e]);
            int s = __ldg(&src[e]);
            int slot = atomicAdd(&g_cursor[d], 1);
            if (slot < BCAP) g_bucket[(size_t)d * BCAP + slot] = s;
        }
        return;
    }

    // ---- projection branch (R3 verbatim) ----
    __shared__ float Wt[FCH * HO];          // [f_local][64], 8KB
    __shared__ float hs[128 * HS_STRIDE];   // [row][f_local] padded, 16.9KB

    const int tid = threadIdx.x;
    const int rg  = tid >> 3;               // 0..15 (8 rows each)
    const int cg  = tid & 7;                // 0..7  (head index, 8 cols)
    const int row0 = blockIdx.x * 128;

    float4 acc0[8], acc1[8];
    #pragma unroll
    for (int j = 0; j < 8; j++) {
        acc0[j] = make_float4(0.f, 0.f, 0.f, 0.f);
        acc1[j] = make_float4(0.f, 0.f, 0.f, 0.f);
    }

    for (int fc = 0; fc < Fin; fc += FCH) {
        for (int i = tid; i < FCH * HO; i += 128) {
            int fl  = i >> 6;
            int col = i & 63;
            int hh  = col >> 3;
            int o   = col & 7;
            Wt[i] = W[(size_t)hh * (Fin * Oo) + (fc + fl) * Oo + o];
        }
        for (int i = tid; i < 128 * (FCH / 4); i += 128) {
            int row  = i >> 3;
            int f4   = i & 7;
            int grow = row0 + row;
            if (grow >= Nn) grow = Nn - 1;          // clamp (harmless dup)
            float4 v = *(const float4*)&h[(size_t)grow * Fin + fc + f4 * 4];
            float* dstp = &hs[row * HS_STRIDE + f4 * 4];
            dstp[0] = v.x; dstp[1] = v.y; dstp[2] = v.z; dstp[3] = v.w;
        }
        __syncthreads();

        #pragma unroll 4
        for (int f = 0; f < FCH; f++) {
            float4 w0 = *(const float4*)&Wt[f * 64 + cg * 8];
            float4 w1 = *(const float4*)&Wt[f * 64 + cg * 8 + 4];
            #pragma unroll
            for (int j = 0; j < 8; j++) {
                float hv = hs[(rg * 8 + j) * HS_STRIDE + f];
                acc0[j].x += hv * w0.x; acc0[j].y += hv * w0.y;
                acc0[j].z += hv * w0.z; acc0[j].w += hv * w0.w;
                acc1[j].x += hv * w1.x; acc1[j].y += hv * w1.y;
                acc1[j].z += hv * w1.z; acc1[j].w += hv * w1.w;
            }
        }
        __syncthreads();
    }

    float4 a1lo = *(const float4*)&a1[cg * 8];
    float4 a1hi = *(const float4*)&a1[cg * 8 + 4];
    float4 a2lo = *(const float4*)&a2[cg * 8];
    float4 a2hi = *(const float4*)&a2[cg * 8 + 4];

    #pragma unroll
    for (int j = 0; j < 8; j++) {
        int row = row0 + rg * 8 + j;
        if (row < Nn) {
            *(float4*)&g_Wh[(size_t)row * HO + cg * 8]     = acc0[j];
            *(float4*)&g_Wh[(size_t)row * HO + cg * 8 + 4] = acc1[j];
            float s1 = acc0[j].x * a1lo.x + acc0[j].y * a1lo.y +
                       acc0[j].z * a1lo.z + acc0[j].w * a1lo.w +
                       acc1[j].x * a1hi.x + acc1[j].y * a1hi.y +
                       acc1[j].z * a1hi.z + acc1[j].w * a1hi.w;
            float s2 = acc0[j].x * a2lo.x + acc0[j].y * a2lo.y +
                       acc0[j].z * a2lo.z + acc0[j].w * a2lo.w +
                       acc1[j].x * a2hi.x + acc1[j].y * a2hi.y +
                       acc1[j].z * a2hi.z + acc1[j].w * a2hi.w;
            g_ssrc[row * Hh + cg] = s1;
            g_sdst[row * Hh + cg] = s2;
        }
    }
}

// ---------------------------------------------------------------------------
// K2: per-dst aggregation. One warp per node; lane owns out[n, lane*2..+1]
// (head = lane>>2). Edge loop unrolled by 8 (two int4 bucket loads -> 8
// independent Wh/ssrc gathers in flight). Resets g_cursor[n] = 0 after
// reading, so the next graph replay's bucket pass starts from zero
// (initial state is the static zero-init).
// ---------------------------------------------------------------------------
__global__ __launch_bounds__(256) void k_agg(float* __restrict__ out) {
    const int warp = (blockIdx.x * 256 + threadIdx.x) >> 5;
    if (warp >= Nn) return;
    const int n    = warp;
    const int lane = threadIdx.x & 31;
    const int head = lane >> 2;

    const float sdst_h = g_sdst[n * Hh + head];
    const int   deg    = min(g_cursor[n], BCAP);
    if (lane == 0) g_cursor[n] = 0;                  // self-clean for replay
    const int4* bkt4   = (const int4*)&g_bucket[(size_t)n * BCAP]; // 16B-aligned
    const float* whp   = g_Wh + lane * 2;

    float2 acc = make_float2(0.f, 0.f);
    float  dsum = 0.f;

    int i = 0;
    for (; i + 8 <= deg; i += 8) {
        int4 sa = __ldg(&bkt4[i >> 2]);
        int4 sb = __ldg(&bkt4[(i >> 2) + 1]);

        float2 w0 = *(const float2*)(whp + (size_t)sa.x * HO);
        float2 w1 = *(const float2*)(whp + (size_t)sa.y * HO);
        float2 w2 = *(const float2*)(whp + (size_t)sa.z * HO);
        float2 w3 = *(const float2*)(whp + (size_t)sa.w * HO);
        float2 w4 = *(const float2*)(whp + (size_t)sb.x * HO);
        float2 w5 = *(const float2*)(whp + (size_t)sb.y * HO);
        float2 w6 = *(const float2*)(whp + (size_t)sb.z * HO);
        float2 w7 = *(const float2*)(whp + (size_t)sb.w * HO);
        float v0 = __ldg(&g_ssrc[sa.x * Hh + head]);
        float v1 = __ldg(&g_ssrc[sa.y * Hh + head]);
        float v2 = __ldg(&g_ssrc[sa.z * Hh + head]);
        float v3 = __ldg(&g_ssrc[sa.w * Hh + head]);
        float v4 = __ldg(&g_ssrc[sb.x * Hh + head]);
        float v5 = __ldg(&g_ssrc[sb.y * Hh + head]);
        float v6 = __ldg(&g_ssrc[sb.z * Hh + head]);
        float v7 = __ldg(&g_ssrc[sb.w * Hh + head]);

        v0 += sdst_h; v1 += sdst_h; v2 += sdst_h; v3 += sdst_h;
        v4 += sdst_h; v5 += sdst_h; v6 += sdst_h; v7 += sdst_h;
        v0 = v0 > 0.f ? v0 : NEG_SLOPE * v0;
        v1 = v1 > 0.f ? v1 : NEG_SLOPE * v1;
        v2 = v2 > 0.f ? v2 : NEG_SLOPE * v2;
        v3 = v3 > 0.f ? v3 : NEG_SLOPE * v3;
        v4 = v4 > 0.f ? v4 : NEG_SLOPE * v4;
        v5 = v5 > 0.f ? v5 : NEG_SLOPE * v5;
        v6 = v6 > 0.f ? v6 : NEG_SLOPE * v6;
        v7 = v7 > 0.f ? v7 : NEG_SLOPE * v7;
        float p0 = __expf(v0), p1 = __expf(v1);
        float p2 = __expf(v2), p3 = __expf(v3);
        float p4 = __expf(v4), p5 = __expf(v5);
        float p6 = __expf(v6), p7 = __expf(v7);

        acc.x += p0 * w0.x + p1 * w1.x + p2 * w2.x + p3 * w3.x
               + p4 * w4.x + p5 * w5.x + p6 * w6.x + p7 * w7.x;
        acc.y += p0 * w0.y + p1 * w1.y + p2 * w2.y + p3 * w3.y
               + p4 * w4.y + p5 * w5.y + p6 * w6.y + p7 * w7.y;
        dsum  += ((p0 + p1) + (p2 + p3)) + ((p4 + p5) + (p6 + p7));
    }
    for (; i + 4 <= deg; i += 4) {
        int4 s4 = __ldg(&bkt4[i >> 2]);
        float2 w0 = *(const float2*)(whp + (size_t)s4.x * HO);
        float2 w1 = *(const float2*)(whp + (size_t)s4.y * HO);
        float2 w2 = *(const float2*)(whp + (size_t)s4.z * HO);
        float2 w3 = *(const float2*)(whp + (size_t)s4.w * HO);
        float v0 = __ldg(&g_ssrc[s4.x * Hh + head]);
        float v1 = __ldg(&g_ssrc[s4.y * Hh + head]);
        float v2 = __ldg(&g_ssrc[s4.z * Hh + head]);
        float v3 = __ldg(&g_ssrc[s4.w * Hh + head]);
        v0 += sdst_h; v1 += sdst_h; v2 += sdst_h; v3 += sdst_h;
        v0 = v0 > 0.f ? v0 : NEG_SLOPE * v0;
        v1 = v1 > 0.f ? v1 : NEG_SLOPE * v1;
        v2 = v2 > 0.f ? v2 : NEG_SLOPE * v2;
        v3 = v3 > 0.f ? v3 : NEG_SLOPE * v3;
        float p0 = __expf(v0), p1 = __expf(v1);
        float p2 = __expf(v2), p3 = __expf(v3);
        acc.x += p0 * w0.x + p1 * w1.x + p2 * w2.x + p3 * w3.x;
        acc.y += p0 * w0.y + p1 * w1.y + p2 * w2.y + p3 * w3.y;
        dsum  += (p0 + p1) + (p2 + p3);
    }
    const int* bkt = (const int*)bkt4;
    for (; i < deg; i++) {
        int s = __ldg(&bkt[i]);
        float2 w = *(const float2*)(whp + (size_t)s * HO);
        float ev = __ldg(&g_ssrc[s * Hh + head]) + sdst_h;
        ev = ev > 0.f ? ev : NEG_SLOPE * ev;
        float pv = __expf(ev);
        acc.x += pv * w.x;
        acc.y += pv * w.y;
        dsum  += pv;
    }

    float inv = 1.0f / fmaxf(dsum, 1e-16f);
    float2 r;
    r.x = acc.x * inv;
    r.y = acc.y * inv;
    *(float2*)&out[(size_t)n * HO + lane * 2] = r;   // coalesced 256B/warp
}

// ---------------------------------------------------------------------------
extern "C" void kernel_launch(void* const* d_in, const int* in_sizes, int n_in,
                              void* d_out, int out_size) {
    const float* h  = (const float*)d_in[0];
    const float* W  = (const float*)d_in[1];
    const float* a1 = (const float*)d_in[2];
    const float* a2 = (const float*)d_in[3];
    const int*  src = (const int*)d_in[4];
    const int*  dst = (const int*)d_in[5];
    float* out = (float*)d_out;

    k_front<<<PROJ_BLOCKS + BUCKET_BLOCKS, 128>>>(h, W, a1, a2, src, dst);
    k_agg<<<(Nn * 32 + 255) / 256, 256>>>(out);
}

// round 10
// speedup vs baseline: 1.0292x; 1.0292x over previous
#include <cuda_runtime.h>
#include <cuda_bf16.h>

// Problem shape (fixed for GAT_40870908789103)
#define Nn   50000
#define Ee   800000
#define Fin  128
#define Hh   8
#define Oo   8
#define HO   64          // H*O
#define NEG_SLOPE 0.2f
#define BCAP 96          // per-node bucket capacity; P(deg>96)~1e-40 for Poisson(16)

#define PROJ_BLOCKS ((Nn + 127) / 128)      // 391
#define BUCKET_BLOCKS 1024

// Scratch (no allocation allowed -> __device__ globals)
// NOTE: g_cursor relies on static zero-init + k_agg self-cleaning reset.
__device__ float g_Wh[(size_t)Nn * HO];       // projected features [N][64]
__device__ float g_ssrc[(size_t)Nn * Hh];     // a1 . Wh[n,h,:]
__device__ float g_sdst[(size_t)Nn * Hh];     // a2 . Wh[n,h,:]
__device__ int   g_cursor[Nn];                // per-node edge counts (zero-init)
__device__ int   g_bucket[(size_t)Nn * BCAP]; // SRC ids grouped by dst

// ---------------------------------------------------------------------------
// K1 (fused front): blocks [0, PROJ_BLOCKS) run the projection GEMM
// (R3 inner loop — verbatim; best measured config). Remaining blocks
// grid-stride over edges bucketing src ids by dst. Proj is FMA/LDS-bound,
// bucket is memory/atomic-bound -> they overlap on different pipes.
// ---------------------------------------------------------------------------
#define FCH 32                      // f-chunk
#define HS_STRIDE 33                // 32 + 1 pad: bank = (row+f) % 32

__global__ __launch_bounds__(128) void k_front(const float* __restrict__ h,
                                               const float* __restrict__ W,
                                               const float* __restrict__ a1,
                                               const float* __restrict__ a2,
                                               const int* __restrict__ src,
                                               const int* __restrict__ dst) {
    if (blockIdx.x >= PROJ_BLOCKS) {
        // ---- bucket branch: grid-stride over edges ----
        const int stride = BUCKET_BLOCKS * 128;
        int e = (blockIdx.x - PROJ_BLOCKS) * 128 + threadIdx.x;
        for (; e < Ee; e += stride) {
            int d = __ldg(&dst[e]);
            int s = __ldg(&src[e]);
            int slot = atomicAdd(&g_cursor[d], 1);
            if (slot < BCAP) g_bucket[(size_t)d * BCAP + slot] = s;
        }
        return;
    }

    // ---- projection branch (R3 verbatim) ----
    __shared__ float Wt[FCH * HO];          // [f_local][64], 8KB
    __shared__ float hs[128 * HS_STRIDE];   // [row][f_local] padded, 16.9KB

    const int tid = threadIdx.x;
    const int rg  = tid >> 3;               // 0..15 (8 rows each)
    const int cg  = tid & 7;                // 0..7  (head index, 8 cols)
    const int row0 = blockIdx.x * 128;

    float4 acc0[8], acc1[8];
    #pragma unroll
    for (int j = 0; j < 8; j++) {
        acc0[j] = make_float4(0.f, 0.f, 0.f, 0.f);
        acc1[j] = make_float4(0.f, 0.f, 0.f, 0.f);
    }

    for (int fc = 0; fc < Fin; fc += FCH) {
        for (int i = tid; i < FCH * HO; i += 128) {
            int fl  = i >> 6;
            int col = i & 63;
            int hh  = col >> 3;
            int o   = col & 7;
            Wt[i] = W[(size_t)hh * (Fin * Oo) + (fc + fl) * Oo + o];
        }
        for (int i = tid; i < 128 * (FCH / 4); i += 128) {
            int row  = i >> 3;
            int f4   = i & 7;
            int grow = row0 + row;
            if (grow >= Nn) grow = Nn - 1;          // clamp (harmless dup)
            float4 v = *(const float4*)&h[(size_t)grow * Fin + fc + f4 * 4];
            float* dstp = &hs[row * HS_STRIDE + f4 * 4];
            dstp[0] = v.x; dstp[1] = v.y; dstp[2] = v.z; dstp[3] = v.w;
        }
        __syncthreads();

        #pragma unroll 4
        for (int f = 0; f < FCH; f++) {
            float4 w0 = *(const float4*)&Wt[f * 64 + cg * 8];
            float4 w1 = *(const float4*)&Wt[f * 64 + cg * 8 + 4];
            #pragma unroll
            for (int j = 0; j < 8; j++) {
                float hv = hs[(rg * 8 + j) * HS_STRIDE + f];
                acc0[j].x += hv * w0.x; acc0[j].y += hv * w0.y;
                acc0[j].z += hv * w0.z; acc0[j].w += hv * w0.w;
                acc1[j].x += hv * w1.x; acc1[j].y += hv * w1.y;
                acc1[j].z += hv * w1.z; acc1[j].w += hv * w1.w;
            }
        }
        __syncthreads();
    }

    float4 a1lo = *(const float4*)&a1[cg * 8];
    float4 a1hi = *(const float4*)&a1[cg * 8 + 4];
    float4 a2lo = *(const float4*)&a2[cg * 8];
    float4 a2hi = *(const float4*)&a2[cg * 8 + 4];

    #pragma unroll
    for (int j = 0; j < 8; j++) {
        int row = row0 + rg * 8 + j;
        if (row < Nn) {
            *(float4*)&g_Wh[(size_t)row * HO + cg * 8]     = acc0[j];
            *(float4*)&g_Wh[(size_t)row * HO + cg * 8 + 4] = acc1[j];
            float s1 = acc0[j].x * a1lo.x + acc0[j].y * a1lo.y +
                       acc0[j].z * a1lo.z + acc0[j].w * a1lo.w +
                       acc1[j].x * a1hi.x + acc1[j].y * a1hi.y +
                       acc1[j].z * a1hi.z + acc1[j].w * a1hi.w;
            float s2 = acc0[j].x * a2lo.x + acc0[j].y * a2lo.y +
                       acc0[j].z * a2lo.z + acc0[j].w * a2lo.w +
                       acc1[j].x * a2hi.x + acc1[j].y * a2hi.y +
                       acc1[j].z * a2hi.z + acc1[j].w * a2hi.w;
            g_ssrc[row * Hh + cg] = s1;
            g_sdst[row * Hh + cg] = s2;
        }
    }
}

// ---------------------------------------------------------------------------
// K2: per-dst aggregation — EXACT R7 unroll-4 body (proven 31.4us; unroll-8
// collapsed MLP because ptxas kept regs=32 and serialized the loads).
// Only addition vs R7: lane-0 resets g_cursor[n] after reading (replaces
// the k_zero_cursor kernel; initial state is static zero-init).
// ---------------------------------------------------------------------------
__global__ __launch_bounds__(256) void k_agg(float* __restrict__ out) {
    const int warp = (blockIdx.x * 256 + threadIdx.x) >> 5;
    if (warp >= Nn) return;
    const int n    = warp;
    const int lane = threadIdx.x & 31;
    const int head = lane >> 2;

    const float sdst_h = g_sdst[n * Hh + head];
    const int   deg    = min(g_cursor[n], BCAP);
    if (lane == 0) g_cursor[n] = 0;                  // self-clean for replay
    const int4* bkt4   = (const int4*)&g_bucket[(size_t)n * BCAP]; // 16B-aligned
    const float* whp   = g_Wh + lane * 2;

    float2 acc = make_float2(0.f, 0.f);
    float  dsum = 0.f;

    int i = 0;
    for (; i + 4 <= deg; i += 4) {
        int4 s4 = __ldg(&bkt4[i >> 2]);

        float2 w0 = *(const float2*)(whp + (size_t)s4.x * HO);
        float2 w1 = *(const float2*)(whp + (size_t)s4.y * HO);
        float2 w2 = *(const float2*)(whp + (size_t)s4.z * HO);
        float2 w3 = *(const float2*)(whp + (size_t)s4.w * HO);
        float v0 = __ldg(&g_ssrc[s4.x * Hh + head]);
        float v1 = __ldg(&g_ssrc[s4.y * Hh + head]);
        float v2 = __ldg(&g_ssrc[s4.z * Hh + head]);
        float v3 = __ldg(&g_ssrc[s4.w * Hh + head]);

        v0 += sdst_h; v1 += sdst_h; v2 += sdst_h; v3 += sdst_h;
        v0 = v0 > 0.f ? v0 : NEG_SLOPE * v0;
        v1 = v1 > 0.f ? v1 : NEG_SLOPE * v1;
        v2 = v2 > 0.f ? v2 : NEG_SLOPE * v2;
        v3 = v3 > 0.f ? v3 : NEG_SLOPE * v3;
        float p0 = __expf(v0), p1 = __expf(v1);
        float p2 = __expf(v2), p3 = __expf(v3);

        acc.x += p0 * w0.x + p1 * w1.x + p2 * w2.x + p3 * w3.x;
        acc.y += p0 * w0.y + p1 * w1.y + p2 * w2.y + p3 * w3.y;
        dsum  += (p0 + p1) + (p2 + p3);
    }
    // tail (<= 3 edges)
    const int* bkt = (const int*)bkt4;
    for (; i < deg; i++) {
        int s = __ldg(&bkt[i]);
        float2 w = *(const float2*)(whp + (size_t)s * HO);
        float ev = __ldg(&g_ssrc[s * Hh + head]) + sdst_h;
        ev = ev > 0.f ? ev : NEG_SLOPE * ev;
        float pv = __expf(ev);
        acc.x += pv * w.x;
        acc.y += pv * w.y;
        dsum  += pv;
    }

    float inv = 1.0f / fmaxf(dsum, 1e-16f);
    float2 r;
    r.x = acc.x * inv;
    r.y = acc.y * inv;
    *(float2*)&out[(size_t)n * HO + lane * 2] = r;   // coalesced 256B/warp
}

// ---------------------------------------------------------------------------
extern "C" void kernel_launch(void* const* d_in, const int* in_sizes, int n_in,
                              void* d_out, int out_size) {
    const float* h  = (const float*)d_in[0];
    const float* W  = (const float*)d_in[1];
    const float* a1 = (const float*)d_in[2];
    const float* a2 = (const float*)d_in[3];
    const int*  src = (const int*)d_in[4];
    const int*  dst = (const int*)d_in[5];
    float* out = (float*)d_out;

    k_front<<<PROJ_BLOCKS + BUCKET_BLOCKS, 128>>>(h, W, a1, a2, src, dst);
    k_agg<<<(Nn * 32 + 255) / 256, 256>>>(out);
}

// round 11
// speedup vs baseline: 2.0370x; 1.9793x over previous
#include <cuda_runtime.h>
#include <cuda_bf16.h>

// Problem shape (fixed for GAT_40870908789103)
#define Nn   50000
#define Ee   800000
#define Fin  128
#define Hh   8
#define Oo   8
#define HO   64          // H*O
#define NEG_SLOPE 0.2f
#define BCAP 96          // per-node bucket capacity; P(deg>96)~1e-40 for Poisson(16)

#define PROJ_BLOCKS ((Nn + 127) / 128)      // 391
#define BUCKET_BLOCKS 1024

// Scratch (no allocation allowed -> __device__ globals)
__device__ float g_Wh[(size_t)Nn * HO];       // projected features [N][64]
__device__ float g_ssrc[(size_t)Nn * Hh];     // a1 . Wh[n,h,:]
__device__ float g_sdst[(size_t)Nn * Hh];     // a2 . Wh[n,h,:]
__device__ int   g_cursor[Nn];                // per-node edge counts
__device__ int   g_bucket[(size_t)Nn * BCAP]; // SRC ids grouped by dst

// ---------------------------------------------------------------------------
// K0: zero per-node cursors (R7 style; must precede the bucket fill)
// ---------------------------------------------------------------------------
__global__ void k_zero_cursor() {
    int i = blockIdx.x * blockDim.x + threadIdx.x;
    if (i < Nn) g_cursor[i] = 0;
}

// ---------------------------------------------------------------------------
// K1 (fused front): blocks [0, PROJ_BLOCKS) run the projection GEMM
// (R3 inner loop — verbatim; best measured config). Remaining blocks
// grid-stride over edges bucketing src ids by dst. Proj is FMA/LDS-bound,
// bucket is memory/atomic-bound -> they overlap on different pipes.
// ---------------------------------------------------------------------------
#define FCH 32                      // f-chunk
#define HS_STRIDE 33                // 32 + 1 pad: bank = (row+f) % 32

__global__ __launch_bounds__(128) void k_front(const float* __restrict__ h,
                                               const float* __restrict__ W,
                                               const float* __restrict__ a1,
                                               const float* __restrict__ a2,
                                               const int* __restrict__ src,
                                               const int* __restrict__ dst) {
    if (blockIdx.x >= PROJ_BLOCKS) {
        // ---- bucket branch: grid-stride over edges ----
        const int stride = BUCKET_BLOCKS * 128;
        int e = (blockIdx.x - PROJ_BLOCKS) * 128 + threadIdx.x;
        for (; e < Ee; e += stride) {
            int d = __ldg(&dst[e]);
            int s = __ldg(&src[e]);
            int slot = atomicAdd(&g_cursor[d], 1);
            if (slot < BCAP) g_bucket[(size_t)d * BCAP + slot] = s;
        }
        return;
    }

    // ---- projection branch (R3 verbatim) ----
    __shared__ float Wt[FCH * HO];          // [f_local][64], 8KB
    __shared__ float hs[128 * HS_STRIDE];   // [row][f_local] padded, 16.9KB

    const int tid = threadIdx.x;
    const int rg  = tid >> 3;               // 0..15 (8 rows each)
    const int cg  = tid & 7;                // 0..7  (head index, 8 cols)
    const int row0 = blockIdx.x * 128;

    float4 acc0[8], acc1[8];
    #pragma unroll
    for (int j = 0; j < 8; j++) {
        acc0[j] = make_float4(0.f, 0.f, 0.f, 0.f);
        acc1[j] = make_float4(0.f, 0.f, 0.f, 0.f);
    }

    for (int fc = 0; fc < Fin; fc += FCH) {
        for (int i = tid; i < FCH * HO; i += 128) {
            int fl  = i >> 6;
            int col = i & 63;
            int hh  = col >> 3;
            int o   = col & 7;
            Wt[i] = W[(size_t)hh * (Fin * Oo) + (fc + fl) * Oo + o];
        }
        for (int i = tid; i < 128 * (FCH / 4); i += 128) {
            int row  = i >> 3;
            int f4   = i & 7;
            int grow = row0 + row;
            if (grow >= Nn) grow = Nn - 1;          // clamp (harmless dup)
            float4 v = *(const float4*)&h[(size_t)grow * Fin + fc + f4 * 4];
            float* dstp = &hs[row * HS_STRIDE + f4 * 4];
            dstp[0] = v.x; dstp[1] = v.y; dstp[2] = v.z; dstp[3] = v.w;
        }
        __syncthreads();

        #pragma unroll 4
        for (int f = 0; f < FCH; f++) {
            float4 w0 = *(const float4*)&Wt[f * 64 + cg * 8];
            float4 w1 = *(const float4*)&Wt[f * 64 + cg * 8 + 4];
            #pragma unroll
            for (int j = 0; j < 8; j++) {
                float hv = hs[(rg * 8 + j) * HS_STRIDE + f];
                acc0[j].x += hv * w0.x; acc0[j].y += hv * w0.y;
                acc0[j].z += hv * w0.z; acc0[j].w += hv * w0.w;
                acc1[j].x += hv * w1.x; acc1[j].y += hv * w1.y;
                acc1[j].z += hv * w1.z; acc1[j].w += hv * w1.w;
            }
        }
        __syncthreads();
    }

    float4 a1lo = *(const float4*)&a1[cg * 8];
    float4 a1hi = *(const float4*)&a1[cg * 8 + 4];
    float4 a2lo = *(const float4*)&a2[cg * 8];
    float4 a2hi = *(const float4*)&a2[cg * 8 + 4];

    #pragma unroll
    for (int j = 0; j < 8; j++) {
        int row = row0 + rg * 8 + j;
        if (row < Nn) {
            *(float4*)&g_Wh[(size_t)row * HO + cg * 8]     = acc0[j];
            *(float4*)&g_Wh[(size_t)row * HO + cg * 8 + 4] = acc1[j];
            float s1 = acc0[j].x * a1lo.x + acc0[j].y * a1lo.y +
                       acc0[j].z * a1lo.z + acc0[j].w * a1lo.w +
                       acc1[j].x * a1hi.x + acc1[j].y * a1hi.y +
                       acc1[j].z * a1hi.z + acc1[j].w * a1hi.w;
            float s2 = acc0[j].x * a2lo.x + acc0[j].y * a2lo.y +
                       acc0[j].z * a2lo.z + acc0[j].w * a2lo.w +
                       acc1[j].x * a2hi.x + acc1[j].y * a2hi.y +
                       acc1[j].z * a2hi.z + acc1[j].w * a2hi.w;
            g_ssrc[row * Hh + cg] = s1;
            g_sdst[row * Hh + cg] = s2;
        }
    }
}

// ---------------------------------------------------------------------------
// K2: per-dst aggregation — BYTE-EXACT R7 body (proven 31.4us).
// NO cursor self-clean here (R8's added store is the prime suspect for the
// 3.3x MLP collapse; bisecting it out this round).
// ---------------------------------------------------------------------------
__global__ __launch_bounds__(256) void k_agg(float* __restrict__ out) {
    const int warp = (blockIdx.x * 256 + threadIdx.x) >> 5;
    if (warp >= Nn) return;
    const int n    = warp;
    const int lane = threadIdx.x & 31;
    const int head = lane >> 2;

    const float sdst_h = g_sdst[n * Hh + head];
    const int   deg    = min(g_cursor[n], BCAP);
    const int4* bkt4   = (const int4*)&g_bucket[(size_t)n * BCAP]; // 16B-aligned
    const float* whp   = g_Wh + lane * 2;

    float2 acc = make_float2(0.f, 0.f);
    float  dsum = 0.f;

    int i = 0;
    for (; i + 4 <= deg; i += 4) {
        int4 s4 = __ldg(&bkt4[i >> 2]);

        float2 w0 = *(const float2*)(whp + (size_t)s4.x * HO);
        float2 w1 = *(const float2*)(whp + (size_t)s4.y * HO);
        float2 w2 = *(const float2*)(whp + (size_t)s4.z * HO);
        float2 w3 = *(const float2*)(whp + (size_t)s4.w * HO);
        float v0 = __ldg(&g_ssrc[s4.x * Hh + head]);
        float v1 = __ldg(&g_ssrc[s4.y * Hh + head]);
        float v2 = __ldg(&g_ssrc[s4.z * Hh + head]);
        float v3 = __ldg(&g_ssrc[s4.w * Hh + head]);

        v0 += sdst_h; v1 += sdst_h; v2 += sdst_h; v3 += sdst_h;
        v0 = v0 > 0.f ? v0 : NEG_SLOPE * v0;
        v1 = v1 > 0.f ? v1 : NEG_SLOPE * v1;
        v2 = v2 > 0.f ? v2 : NEG_SLOPE * v2;
        v3 = v3 > 0.f ? v3 : NEG_SLOPE * v3;
        float p0 = __expf(v0), p1 = __expf(v1);
        float p2 = __expf(v2), p3 = __expf(v3);

        acc.x += p0 * w0.x + p1 * w1.x + p2 * w2.x + p3 * w3.x;
        acc.y += p0 * w0.y + p1 * w1.y + p2 * w2.y + p3 * w3.y;
        dsum  += (p0 + p1) + (p2 + p3);
    }
    // tail (<= 3 edges)
    const int* bkt = (const int*)bkt4;
    for (; i < deg; i++) {
        int s = __ldg(&bkt[i]);
        float2 w = *(const float2*)(whp + (size_t)s * HO);
        float ev = __ldg(&g_ssrc[s * Hh + head]) + sdst_h;
        ev = ev > 0.f ? ev : NEG_SLOPE * ev;
        float pv = __expf(ev);
        acc.x += pv * w.x;
        acc.y += pv * w.y;
        dsum  += pv;
    }

    float inv = 1.0f / fmaxf(dsum, 1e-16f);
    float2 r;
    r.x = acc.x * inv;
    r.y = acc.y * inv;
    *(float2*)&out[(size_t)n * HO + lane * 2] = r;   // coalesced 256B/warp
}

// ---------------------------------------------------------------------------
extern "C" void kernel_launch(void* const* d_in, const int* in_sizes, int n_in,
                              void* d_out, int out_size) {
    const float* h  = (const float*)d_in[0];
    const float* W  = (const float*)d_in[1];
    const float* a1 = (const float*)d_in[2];
    const float* a2 = (const float*)d_in[3];
    const int*  src = (const int*)d_in[4];
    const int*  dst = (const int*)d_in[5];
    float* out = (float*)d_out;

    k_zero_cursor<<<(Nn + 255) / 256, 256>>>();
    k_front<<<PROJ_BLOCKS + BUCKET_BLOCKS, 128>>>(h, W, a1, a2, src, dst);
    k_agg<<<(Nn * 32 + 255) / 256, 256>>>(out);
}

// round 12
// speedup vs baseline: 2.0429x; 1.0029x over previous
#include <cuda_runtime.h>
#include <cuda_bf16.h>

// Problem shape (fixed for GAT_40870908789103)
#define Nn   50000
#define Ee   800000
#define Fin  128
#define Hh   8
#define Oo   8
#define HO   64          // H*O
#define NEG_SLOPE 0.2f
#define BCAP 96          // per-node bucket capacity; P(deg>96)~1e-40 for Poisson(16)

#define PROJ_BLOCKS ((Nn + 127) / 128)      // 391
#define BUCKET_BLOCKS 1024

// Scratch (no allocation allowed -> __device__ globals)
__device__ float g_Wh[(size_t)Nn * HO];       // projected features [N][64]
__device__ float g_ssrc[(size_t)Nn * Hh];     // a1 . Wh[n,h,:]
__device__ float g_sdst[(size_t)Nn * Hh];     // a2 . Wh[n,h,:]
__device__ int   g_cursor[Nn];                // per-node edge counts
__device__ int   g_bucket[(size_t)Nn * BCAP + 4]; // SRC ids by dst (+4 pad for prefetch over-read)

// ---------------------------------------------------------------------------
// K0: zero per-node cursors (vectorized; must precede the bucket fill)
// ---------------------------------------------------------------------------
__global__ void k_zero_cursor() {
    int i = blockIdx.x * blockDim.x + threadIdx.x;     // over 12500 int4
    if (i < Nn / 4) ((int4*)g_cursor)[i] = make_int4(0, 0, 0, 0);
}

// ---------------------------------------------------------------------------
// K1 (fused front): blocks [0, PROJ_BLOCKS) run the projection GEMM
// (R3 inner loop — verbatim; best measured config). Remaining blocks
// grid-stride over edges bucketing src ids by dst. Proj is FMA/LDS-bound,
// bucket is memory/atomic-bound -> they overlap on different pipes.
// ---------------------------------------------------------------------------
#define FCH 32                      // f-chunk
#define HS_STRIDE 33                // 32 + 1 pad: bank = (row+f) % 32

__global__ __launch_bounds__(128) void k_front(const float* __restrict__ h,
                                               const float* __restrict__ W,
                                               const float* __restrict__ a1,
                                               const float* __restrict__ a2,
                                               const int* __restrict__ src,
                                               const int* __restrict__ dst) {
    if (blockIdx.x >= PROJ_BLOCKS) {
        // ---- bucket branch: grid-stride over edges ----
        const int stride = BUCKET_BLOCKS * 128;
        int e = (blockIdx.x - PROJ_BLOCKS) * 128 + threadIdx.x;
        for (; e < Ee; e += stride) {
            int d = __ldg(&dst[e]);
            int s = __ldg(&src[e]);
            int slot = atomicAdd(&g_cursor[d], 1);
            if (slot < BCAP) g_bucket[(size_t)d * BCAP + slot] = s;
        }
        return;
    }

    // ---- projection branch (R3 verbatim) ----
    __shared__ float Wt[FCH * HO];          // [f_local][64], 8KB
    __shared__ float hs[128 * HS_STRIDE];   // [row][f_local] padded, 16.9KB

    const int tid = threadIdx.x;
    const int rg  = tid >> 3;               // 0..15 (8 rows each)
    const int cg  = tid & 7;                // 0..7  (head index, 8 cols)
    const int row0 = blockIdx.x * 128;

    float4 acc0[8], acc1[8];
    #pragma unroll
    for (int j = 0; j < 8; j++) {
        acc0[j] = make_float4(0.f, 0.f, 0.f, 0.f);
        acc1[j] = make_float4(0.f, 0.f, 0.f, 0.f);
    }

    for (int fc = 0; fc < Fin; fc += FCH) {
        for (int i = tid; i < FCH * HO; i += 128) {
            int fl  = i >> 6;
            int col = i & 63;
            int hh  = col >> 3;
            int o   = col & 7;
            Wt[i] = W[(size_t)hh * (Fin * Oo) + (fc + fl) * Oo + o];
        }
        for (int i = tid; i < 128 * (FCH / 4); i += 128) {
            int row  = i >> 3;
            int f4   = i & 7;
            int grow = row0 + row;
            if (grow >= Nn) grow = Nn - 1;          // clamp (harmless dup)
            float4 v = *(const float4*)&h[(size_t)grow * Fin + fc + f4 * 4];
            float* dstp = &hs[row * HS_STRIDE + f4 * 4];
            dstp[0] = v.x; dstp[1] = v.y; dstp[2] = v.z; dstp[3] = v.w;
        }
        __syncthreads();

        #pragma unroll 4
        for (int f = 0; f < FCH; f++) {
            float4 w0 = *(const float4*)&Wt[f * 64 + cg * 8];
            float4 w1 = *(const float4*)&Wt[f * 64 + cg * 8 + 4];
            #pragma unroll
            for (int j = 0; j < 8; j++) {
                float hv = hs[(rg * 8 + j) * HS_STRIDE + f];
                acc0[j].x += hv * w0.x; acc0[j].y += hv * w0.y;
                acc0[j].z += hv * w0.z; acc0[j].w += hv * w0.w;
                acc1[j].x += hv * w1.x; acc1[j].y += hv * w1.y;
                acc1[j].z += hv * w1.z; acc1[j].w += hv * w1.w;
            }
        }
        __syncthreads();
    }

    float4 a1lo = *(const float4*)&a1[cg * 8];
    float4 a1hi = *(const float4*)&a1[cg * 8 + 4];
    float4 a2lo = *(const float4*)&a2[cg * 8];
    float4 a2hi = *(const float4*)&a2[cg * 8 + 4];

    #pragma unroll
    for (int j = 0; j < 8; j++) {
        int row = row0 + rg * 8 + j;
        if (row < Nn) {
            *(float4*)&g_Wh[(size_t)row * HO + cg * 8]     = acc0[j];
            *(float4*)&g_Wh[(size_t)row * HO + cg * 8 + 4] = acc1[j];
            float s1 = acc0[j].x * a1lo.x + acc0[j].y * a1lo.y +
                       acc0[j].z * a1lo.z + acc0[j].w * a1lo.w +
                       acc1[j].x * a1hi.x + acc1[j].y * a1hi.y +
                       acc1[j].z * a1hi.z + acc1[j].w * a1hi.w;
            float s2 = acc0[j].x * a2lo.x + acc0[j].y * a2lo.y +
                       acc0[j].z * a2lo.z + acc0[j].w * a2lo.w +
                       acc1[j].x * a2hi.x + acc1[j].y * a2hi.y +
                       acc1[j].z * a2hi.z + acc1[j].w * a2hi.w;
            g_ssrc[row * Hh + cg] = s1;
            g_sdst[row * Hh + cg] = s2;
        }
    }
}

// ---------------------------------------------------------------------------
// K2: per-dst aggregation — R7 body + 1-deep bucket-word prefetch.
// The next int4 of src ids is loaded while the current 4 edges' gathers
// and exp/FMA computes run, collapsing the 2-round-trip critical path
// (bkt -> gathers) toward 1 round trip per 4 edges. NO stores before/in
// the loop (R8 lesson). Over-read of the final prefetch is covered by the
// +4 int padding on g_bucket.
// ---------------------------------------------------------------------------
__global__ __launch_bounds__(256) void k_agg(float* __restrict__ out) {
    const int warp = (blockIdx.x * 256 + threadIdx.x) >> 5;
    if (warp >= Nn) return;
    const int n    = warp;
    const int lane = threadIdx.x & 31;
    const int head = lane >> 2;

    const float sdst_h = g_sdst[n * Hh + head];
    const int   deg    = min(g_cursor[n], BCAP);
    const int4* bkt4   = (const int4*)&g_bucket[(size_t)n * BCAP]; // 16B-aligned
    const float* whp   = g_Wh + lane * 2;

    float2 acc = make_float2(0.f, 0.f);
    float  dsum = 0.f;

    const int nIter = deg >> 2;            // full groups of 4
    if (nIter > 0) {
        int4 sc = __ldg(&bkt4[0]);
        for (int it = 0; it < nIter; it++) {
            int4 sn = __ldg(&bkt4[it + 1]);   // prefetch (padded; always safe)

            float2 w0 = *(const float2*)(whp + (size_t)sc.x * HO);
            float2 w1 = *(const float2*)(whp + (size_t)sc.y * HO);
            float2 w2 = *(const float2*)(whp + (size_t)sc.z * HO);
            float2 w3 = *(const float2*)(whp + (size_t)sc.w * HO);
            float v0 = __ldg(&g_ssrc[sc.x * Hh + head]);
            float v1 = __ldg(&g_ssrc[sc.y * Hh + head]);
            float v2 = __ldg(&g_ssrc[sc.z * Hh + head]);
            float v3 = __ldg(&g_ssrc[sc.w * Hh + head]);

            v0 += sdst_h; v1 += sdst_h; v2 += sdst_h; v3 += sdst_h;
            v0 = v0 > 0.f ? v0 : NEG_SLOPE * v0;
            v1 = v1 > 0.f ? v1 : NEG_SLOPE * v1;
            v2 = v2 > 0.f ? v2 : NEG_SLOPE * v2;
            v3 = v3 > 0.f ? v3 : NEG_SLOPE * v3;
            float p0 = __expf(v0), p1 = __expf(v1);
            float p2 = __expf(v2), p3 = __expf(v3);

            acc.x += p0 * w0.x + p1 * w1.x + p2 * w2.x + p3 * w3.x;
            acc.y += p0 * w0.y + p1 * w1.y + p2 * w2.y + p3 * w3.y;
            dsum  += (p0 + p1) + (p2 + p3);

            sc = sn;
        }
    }
    // tail (<= 3 edges)
    const int* bkt = (const int*)bkt4;
    for (int i = nIter * 4; i < deg; i++) {
        int s = __ldg(&bkt[i]);
        float2 w = *(const float2*)(whp + (size_t)s * HO);
        float ev = __ldg(&g_ssrc[s * Hh + head]) + sdst_h;
        ev = ev > 0.f ? ev : NEG_SLOPE * ev;
        float pv = __expf(ev);
        acc.x += pv * w.x;
        acc.y += pv * w.y;
        dsum  += pv;
    }

    float inv = 1.0f / fmaxf(dsum, 1e-16f);
    float2 r;
    r.x = acc.x * inv;
    r.y = acc.y * inv;
    *(float2*)&out[(size_t)n * HO + lane * 2] = r;   // coalesced 256B/warp
}

// ---------------------------------------------------------------------------
extern "C" void kernel_launch(void* const* d_in, const int* in_sizes, int n_in,
                              void* d_out, int out_size) {
    const float* h  = (const float*)d_in[0];
    const float* W  = (const float*)d_in[1];
    const float* a1 = (const float*)d_in[2];
    const float* a2 = (const float*)d_in[3];
    const int*  src = (const int*)d_in[4];
    const int*  dst = (const int*)d_in[5];
    float* out = (float*)d_out;

    k_zero_cursor<<<(Nn / 4 + 255) / 256, 256>>>();
    k_front<<<PROJ_BLOCKS + BUCKET_BLOCKS, 128>>>(h, W, a1, a2, src, dst);
    k_agg<<<(Nn * 32 + 255) / 256, 256>>>(out);
}